// round 3
// baseline (speedup 1.0000x reference)
#include <cuda_runtime.h>
#include <math.h>

#define B_ 4096
#define T_ 40
#define BT_ (B_*T_)

__device__ float g_base1[B_*128];

// ---------- packed f32x2 helpers ----------
__device__ __forceinline__ unsigned long long pk2(float lo, float hi){
    return ((unsigned long long)__float_as_uint(hi) << 32) | (unsigned long long)__float_as_uint(lo);
}
__device__ __forceinline__ unsigned long long fma2(unsigned long long a, unsigned long long b, unsigned long long c){
    unsigned long long d;
    asm("fma.rn.f32x2 %0, %1, %2, %3;" : "=l"(d) : "l"(a), "l"(b), "l"(c));
    return d;
}
__device__ __forceinline__ unsigned long long add2(unsigned long long a, unsigned long long b){
    unsigned long long d;
    asm("add.rn.f32x2 %0, %1, %2;" : "=l"(d) : "l"(a), "l"(b));
    return d;
}
__device__ __forceinline__ float red2(unsigned long long a){
    float lo = __uint_as_float((unsigned)(a & 0xffffffffULL));
    float hi = __uint_as_float((unsigned)(a >> 32));
    return lo + hi;
}

// 128-long dot: weights packed in 64 regs per thread, input broadcast from smem
__device__ __forceinline__ float matvec128(const unsigned long long* w, const float* hbuf){
    unsigned long long a0=0ULL,a1=0ULL,a2=0ULL,a3=0ULL;
    const ulonglong2* hp = reinterpret_cast<const ulonglong2*>(hbuf);
    #pragma unroll
    for (int i=0;i<32;i+=2){
        ulonglong2 p = hp[i];
        a0 = fma2(p.x, w[2*i+0], a0);
        a1 = fma2(p.y, w[2*i+1], a1);
        ulonglong2 q = hp[i+1];
        a2 = fma2(q.x, w[2*i+2], a2);
        a3 = fma2(q.y, w[2*i+3], a3);
    }
    return red2(add2(add2(a0,a1), add2(a2,a3)));
}

// ---------- base1 precompute: base1 = [pb, eh] @ W1[0:192] + b1 ----------
__global__ void base1_kernel(const float* __restrict__ pb, const float* __restrict__ eh,
                             const float* __restrict__ W1, const float* __restrict__ b1){
    __shared__ float sin_[16][192];
    const int jj = threadIdx.x;
    const int r0 = blockIdx.x * 16;
    for (int r=0;r<16;r++){
        for (int k=jj; k<192; k+=128){
            sin_[r][k] = (k < 64) ? pb[(size_t)(r0+r)*64 + k]
                                  : eh[(size_t)(r0+r)*128 + (k-64)];
        }
    }
    __syncthreads();
    float acc[16];
    const float bb = b1[jj];
    #pragma unroll
    for (int r=0;r<16;r++) acc[r]=bb;
    for (int k=0;k<192;k++){
        float wv = W1[k*128+jj];
        #pragma unroll
        for (int r=0;r<16;r++) acc[r] = fmaf(sin_[r][k], wv, acc[r]);
    }
    #pragma unroll
    for (int r=0;r<16;r++) g_base1[(size_t)(r0+r)*128 + jj] = acc[r];
}

// ---------- main persistent rollout kernel ----------
__global__ void __launch_bounds__(256,1) rollout_kernel(
    const float* __restrict__ idm_params,
    const float* __restrict__ idm_s,
    const float* __restrict__ mcs,
    const float* __restrict__ W1,
    const float* __restrict__ W2,
    const float* __restrict__ b2,
    const float* __restrict__ W3,
    const float* __restrict__ b3,
    const float* __restrict__ Wf,
    const float* __restrict__ bf,
    const float* __restrict__ Wm,
    const float* __restrict__ bm,
    const float* __restrict__ smean,
    const float* __restrict__ svar,
    float* __restrict__ out)
{
    __shared__ __align__(16) float h1s[2][128];
    __shared__ __align__(16) float h2s[2][128];
    __shared__ float red_[8];

    const int tid  = threadIdx.x;
    const int half = tid >> 7;     // 0: owns W2 (layer2). 1: owns W3 (layer3 + epilogue)
    const int j    = tid & 127;

    // load weight column into registers (packed pairs along k)
    unsigned long long w[64];
    {
        const float* Wsrc = half ? W3 : W2;
        #pragma unroll
        for (int i=0;i<64;i++){
            float lo = Wsrc[(2*i+0)*128 + j];
            float hi = Wsrc[(2*i+1)*128 + j];
            w[i] = pk2(lo, hi);
        }
    }
    const float bias = half ? b3[j] : b2[j];
    const float wfj = Wf[j], wmj = Wm[j];
    const float bfv = bf[0], bmv = bm[0];

    const float w1e0 = W1[192*128+j], w1e1 = W1[193*128+j], w1e2 = W1[194*128+j];
    const float w1e3 = W1[195*128+j], w1e4 = W1[196*128+j], w1e5 = W1[197*128+j];
    const float w1m0 = W1[198*128+j], w1m1 = W1[199*128+j], w1m2 = W1[200*128+j];

    const float m0=smean[0], m1=smean[1], m2=smean[2], m3=smean[3], m4=smean[4], m5=smean[5];
    const float is0=1.0f/sqrtf(svar[0]), is1=1.0f/sqrtf(svar[1]), is2=1.0f/sqrtf(svar[2]);
    const float is3=1.0f/sqrtf(svar[3]), is4=1.0f/sqrtf(svar[4]), is5=1.0f/sqrtf(svar[5]);

    // h1 for step t: env from state (v,x) entering t and s_t, plus merger context
    auto compute_h1 = [&](float v, float x, const float* s, const float* mcp, float base)->float{
        float fv = s[1], mv = s[2], fx = s[4], mx = s[5], mex = s[10];
        bool  me = (mex > 0.5f);
        float em_dx = me ? (mx - x) : 70.0f;
        float em_dv = me ? (v - mv) : 0.0f;
        float e0 = (v - m0)*is0;
        float e1 = (fv - m1)*is1;
        float e2 = ((v - fv) - m2)*is2;
        float e3 = ((fx - x) - m3)*is3;
        float e4 = (em_dv - m4)*is4;
        float e5 = (em_dx - m5)*is5;
        float a = base;
        a = fmaf(e0,w1e0,a); a = fmaf(e1,w1e1,a); a = fmaf(e2,w1e2,a);
        a = fmaf(e3,w1e3,a); a = fmaf(e4,w1e4,a); a = fmaf(e5,w1e5,a);
        a = fmaf(mcp[0],w1m0,a); a = fmaf(mcp[1],w1m1,a); a = fmaf(mcp[2],w1m2,a);
        return fmaxf(a, 0.3f*a);   // leaky_relu(0.3)
    };

    auto idm_act = [](float v, float dv, float dx,
                      float inv_desv, float tgap, float jamx, float mact, float invden)->float{
        float dxc = 0.1f + fmaxf(dx, 0.0f);
        float gap = fmaxf(fmaf(tgap, v, jamx) + v*dv*invden, 0.0f);
        float vr  = v*inv_desv; float vr2 = vr*vr;
        float gr  = gap/dxc;
        float a   = mact*(1.0f - vr2*vr2 - gr*gr);
        return fminf(fmaxf(a,-50.0f),50.0f);
    };

    // full per-step epilogue for half2: heads, attention, IDM, state update, next h1
    auto epilogue = [&](float h3j, int row, int t, float &v, float &x,
                        float inv_desv, float tgap, float jamx, float mact, float invden,
                        float base, int dstbuf){
        float pf = h3j*wfj, pm = h3j*wmj;
        #pragma unroll
        for (int o=16;o;o>>=1){
            pf += __shfl_xor_sync(0xffffffffu, pf, o);
            pm += __shfl_xor_sync(0xffffffffu, pm, o);
        }
        int wl = j >> 5;
        if ((j & 31)==0){ red_[2*wl] = pf; red_[2*wl+1] = pm; }
        asm volatile("bar.sync 1, 128;" ::: "memory");   // half2-only barrier
        float lf = (red_[0]+red_[2]) + (red_[4]+red_[6]);
        float lm = (red_[1]+red_[3]) + (red_[5]+red_[7]);
        float d  = 5.0f*((lf + bfv) - (lm + bmv));
        float e  = expf(-d);
        float fatt = 1.0f/(1.0f+e);      // f_s/(f_s+m_s), stable form
        float matt = e*fatt;

        const float* s = idm_s + (size_t)(row*T_ + t)*11;
        float fv = s[1], mv = s[2], fx = s[4], mx = s[5], mex = s[10];
        bool  me = (mex > 0.5f);
        float ef_dx = fx - x,  ef_dv = v - fv;
        float em_dx = me ? (mx - x) : 70.0f;
        float em_dv = me ? (v - mv) : 0.0f;
        float efa = idm_act(v, ef_dv, ef_dx, inv_desv, tgap, jamx, mact, invden);
        float ema = idm_act(v, em_dv, em_dx, inv_desv, tgap, jamx, mact, invden);
        float act = fatt*efa + matt*ema;

        if (j == 0){
            int o = row*T_ + t;
            out[o]         = fminf(fmaxf(act,-5.4f),5.4f);
            out[BT_ + o]   = fatt;
            out[2*BT_ + o] = matt;
        }
        // state update (recurrence uses unclipped act)
        v = fmaf(act, 0.1f, v);
        x = x + v*0.1f + act*0.005f;

        // build h1 for next step
        int tn = (t+1 < T_) ? (t+1) : (T_-1);
        const float* sn  = idm_s + (size_t)(row*T_ + tn)*11;
        const float* mcn = mcs   + (size_t)(row*T_ + tn)*3;
        h1s[dstbuf][j] = compute_h1(v, x, sn, mcn, base);
    };

    for (int pair = blockIdx.x; pair < B_/2; pair += gridDim.x){
        const int rowA = 2*pair, rowB = rowA + 1;

        const float* pA = idm_params + (size_t)rowA*5;
        const float* pB = idm_params + (size_t)rowB*5;
        float invdvA = 1.0f/pA[0], tgapA = pA[1], jamxA = pA[2], mactA = pA[3];
        float invdnA = 1.0f/(2.0f*sqrtf(pA[3]*pA[4]));
        float invdvB = 1.0f/pB[0], tgapB = pB[1], jamxB = pB[2], mactB = pB[3];
        float invdnB = 1.0f/(2.0f*sqrtf(pB[3]*pB[4]));

        float baseA = g_base1[(size_t)rowA*128 + j];
        float baseB = g_base1[(size_t)rowB*128 + j];

        float vA = idm_s[(size_t)(rowA*T_)*11 + 0];
        float xA = idm_s[(size_t)(rowA*T_)*11 + 3];
        float vB = idm_s[(size_t)(rowB*T_)*11 + 0];
        float xB = idm_s[(size_t)(rowB*T_)*11 + 3];

        // init h1 for t=0 (half1 builds row A, half2 builds row B)
        if (half == 0){
            h1s[0][j] = compute_h1(vA, xA, idm_s + (size_t)(rowA*T_)*11,
                                   mcs + (size_t)(rowA*T_)*3, baseA);
        } else {
            h1s[1][j] = compute_h1(vB, xB, idm_s + (size_t)(rowB*T_)*11,
                                   mcs + (size_t)(rowB*T_)*3, baseB);
        }
        __syncthreads();

        // prologue: h2B(0)
        if (half == 0){
            float acc = matvec128(w, h1s[1]) + bias;
            h2s[1][j] = fmaxf(acc, 0.3f*acc);
        }
        __syncthreads();

        for (int t = 0; t < T_; t++){
            // even phase: half1 -> h2A(t);  half2 -> h3B(t) + epilogue B
            if (half == 0){
                float acc = matvec128(w, h1s[0]) + bias;
                h2s[0][j] = fmaxf(acc, 0.3f*acc);
            } else {
                float acc = matvec128(w, h2s[1]) + bias;
                float h3j = fmaxf(acc, 0.3f*acc);
                epilogue(h3j, rowB, t, vB, xB, invdvB, tgapB, jamxB, mactB, invdnB, baseB, 1);
            }
            __syncthreads();
            // odd phase: half1 -> h2B(t+1);  half2 -> h3A(t) + epilogue A
            if (half == 0){
                float acc = matvec128(w, h1s[1]) + bias;
                h2s[1][j] = fmaxf(acc, 0.3f*acc);
            } else {
                float acc = matvec128(w, h2s[0]) + bias;
                float h3j = fmaxf(acc, 0.3f*acc);
                epilogue(h3j, rowA, t, vA, xA, invdvA, tgapA, jamxA, mactA, invdnA, baseA, 0);
            }
            __syncthreads();
        }
    }
}

extern "C" void kernel_launch(void* const* d_in, const int* in_sizes, int n_in,
                              void* d_out, int out_size) {
    (void)in_sizes; (void)n_in; (void)out_size;
    const float* idm_params = (const float*)d_in[0];
    const float* pb         = (const float*)d_in[1];
    const float* eh         = (const float*)d_in[2];
    const float* idm_s      = (const float*)d_in[3];
    const float* mcs        = (const float*)d_in[4];
    const float* W1         = (const float*)d_in[5];
    const float* b1         = (const float*)d_in[6];
    const float* W2         = (const float*)d_in[7];
    const float* b2         = (const float*)d_in[8];
    const float* W3         = (const float*)d_in[9];
    const float* b3         = (const float*)d_in[10];
    const float* Wf         = (const float*)d_in[11];
    const float* bf         = (const float*)d_in[12];
    const float* Wm         = (const float*)d_in[13];
    const float* bm         = (const float*)d_in[14];
    const float* smean      = (const float*)d_in[15];
    const float* svar       = (const float*)d_in[16];
    float* out = (float*)d_out;

    base1_kernel<<<B_/16, 128>>>(pb, eh, W1, b1);
    rollout_kernel<<<152, 256>>>(idm_params, idm_s, mcs, W1, W2, b2, W3, b3,
                                 Wf, bf, Wm, bm, smean, svar, out);
}

// round 8
// speedup vs baseline: 2.2246x; 2.2246x over previous
#include <cuda_runtime.h>
#include <math.h>

#define B_ 4096
#define T_ 40
#define BT_ (B_*T_)
#define G_ 14
#define NCTA ((B_ + 2*G_ - 1)/(2*G_))   /* 147 */

__device__ float g_base1[B_*128];

// ---------- packed f32x2 helpers ----------
__device__ __forceinline__ unsigned long long pk2(float lo, float hi){
    return ((unsigned long long)__float_as_uint(hi) << 32) | (unsigned long long)__float_as_uint(lo);
}
__device__ __forceinline__ unsigned long long fma2(unsigned long long a, unsigned long long b, unsigned long long c){
    unsigned long long d;
    asm("fma.rn.f32x2 %0, %1, %2, %3;" : "=l"(d) : "l"(a), "l"(b), "l"(c));
    return d;
}
__device__ __forceinline__ unsigned long long add2(unsigned long long a, unsigned long long b){
    unsigned long long d;
    asm("add.rn.f32x2 %0, %1, %2;" : "=l"(d) : "l"(a), "l"(b));
    return d;
}
__device__ __forceinline__ float red2(unsigned long long a){
    float lo = __uint_as_float((unsigned)(a & 0xffffffffULL));
    float hi = __uint_as_float((unsigned)(a >> 32));
    return lo + hi;
}

// 128-long dot: weights packed in 64 regs per thread, input broadcast from smem
__device__ __forceinline__ float matvec128(const unsigned long long* w, const float* hbuf){
    unsigned long long a0=0ULL,a1=0ULL,a2=0ULL,a3=0ULL;
    const ulonglong2* hp = reinterpret_cast<const ulonglong2*>(hbuf);
    #pragma unroll
    for (int i=0;i<32;i+=2){
        ulonglong2 p = hp[i];
        a0 = fma2(p.x, w[2*i+0], a0);
        a1 = fma2(p.y, w[2*i+1], a1);
        ulonglong2 q = hp[i+1];
        a2 = fma2(q.x, w[2*i+2], a2);
        a3 = fma2(q.y, w[2*i+3], a3);
    }
    return red2(add2(add2(a0,a1), add2(a2,a3)));
}

// ---------- base1 precompute: base1 = [pb, eh] @ W1[0:192] + b1 ----------
__global__ void base1_kernel(const float* __restrict__ pb, const float* __restrict__ eh,
                             const float* __restrict__ W1, const float* __restrict__ b1){
    __shared__ float sin_[16][192];
    const int jj = threadIdx.x;
    const int r0 = blockIdx.x * 16;
    for (int r=0;r<16;r++){
        for (int k=jj; k<192; k+=128){
            sin_[r][k] = (k < 64) ? pb[(size_t)(r0+r)*64 + k]
                                  : eh[(size_t)(r0+r)*128 + (k-64)];
        }
    }
    __syncthreads();
    float acc[16];
    const float bb = b1[jj];
    #pragma unroll
    for (int r=0;r<16;r++) acc[r]=bb;
    for (int k=0;k<192;k++){
        float wv = W1[k*128+jj];
        #pragma unroll
        for (int r=0;r<16;r++) acc[r] = fmaf(sin_[r][k], wv, acc[r]);
    }
    #pragma unroll
    for (int r=0;r<16;r++) g_base1[(size_t)(r0+r)*128 + jj] = acc[r];
}

// ---------- main persistent rollout kernel ----------
__global__ void __launch_bounds__(256,1) rollout_kernel(
    const float* __restrict__ idm_params,
    const float* __restrict__ idm_s,
    const float* __restrict__ mcs,
    const float* __restrict__ W1,
    const float* __restrict__ W2,
    const float* __restrict__ b2,
    const float* __restrict__ W3,
    const float* __restrict__ b3,
    const float* __restrict__ Wf,
    const float* __restrict__ bf,
    const float* __restrict__ Wm,
    const float* __restrict__ bm,
    const float* __restrict__ smean,
    const float* __restrict__ svar,
    float* __restrict__ out)
{
    __shared__ __align__(16) float h1s[2][G_][128];
    __shared__ __align__(16) float h2s[2][G_][128];
    __shared__ __align__(16) float base_s[2][G_][128];
    __shared__ float red_s[G_][8];
    __shared__ float extra_s[2][G_][9];

    const int tid  = threadIdx.x;
    const int half = tid >> 7;     // 0: owns W2 (layer2). 1: owns W3 (layer3 + epilogue)
    const int j    = tid & 127;
    const int r0   = blockIdx.x * (2*G_);

    // weight column into registers (packed pairs along k)
    unsigned long long w[64];
    {
        const float* Wsrc = half ? W3 : W2;
        #pragma unroll
        for (int i=0;i<64;i++){
            w[i] = pk2(Wsrc[(2*i+0)*128 + j], Wsrc[(2*i+1)*128 + j]);
        }
    }
    const float bias = half ? b3[j] : b2[j];
    const float wfj = Wf[j], wmj = Wm[j];
    const float bfv = bf[0], bmv = bm[0];

    const float w1e0 = W1[192*128+j], w1e1 = W1[193*128+j], w1e2 = W1[194*128+j];
    const float w1e3 = W1[195*128+j], w1e4 = W1[196*128+j], w1e5 = W1[197*128+j];
    const float w1m0 = W1[198*128+j], w1m1 = W1[199*128+j], w1m2 = W1[200*128+j];

    const float m0=smean[0], m1=smean[1], m2=smean[2], m3=smean[3], m4=smean[4], m5=smean[5];
    const float is0=1.0f/sqrtf(svar[0]), is1=1.0f/sqrtf(svar[1]), is2=1.0f/sqrtf(svar[2]);
    const float is3=1.0f/sqrtf(svar[3]), is4=1.0f/sqrtf(svar[4]), is5=1.0f/sqrtf(svar[5]);

    // stage base1 for all 28 rows into shared
    for (int idx = tid; idx < 2*G_*128; idx += 256){
        int grp = idx / (G_*128);
        int rem = idx - grp*(G_*128);
        int g = rem >> 7, jj = rem & 127;
        int row = r0 + grp*G_ + g; if (row >= B_) row = B_-1;
        base_s[grp][g][jj] = g_base1[(size_t)row*128 + jj];
    }

    // per-row state held in half2 threads j<G_ (one thread per row, both groups)
    float v_[2], x_[2], invdv_[2], tgap_[2], jamx_[2], mact_[2], invdn_[2];
    int   rowi_[2]; bool valid_[2];
    if (half == 1 && j < G_){
        #pragma unroll
        for (int grp=0; grp<2; grp++){
            int row = r0 + grp*G_ + j;
            valid_[grp] = (row < B_);
            if (row >= B_) row = B_-1;
            rowi_[grp] = row;
            const float* p = idm_params + (size_t)row*5;
            invdv_[grp] = 1.0f/p[0]; tgap_[grp] = p[1]; jamx_[grp] = p[2]; mact_[grp] = p[3];
            invdn_[grp] = 1.0f/(2.0f*sqrtf(p[3]*p[4]));
            const float* s0 = idm_s + (size_t)row*T_*11;
            float vv = s0[0], xx = s0[3];
            v_[grp] = vv; x_[grp] = xx;
            float fv = s0[1], mv = s0[2], fx = s0[4], mx = s0[5], mex = s0[10];
            bool  me = (mex > 0.5f);
            float edx = me ? (mx - xx) : 70.0f;
            float edv = me ? (vv - mv) : 0.0f;
            const float* mc0 = mcs + (size_t)row*T_*3;
            extra_s[grp][j][0] = (vv - m0)*is0;
            extra_s[grp][j][1] = (fv - m1)*is1;
            extra_s[grp][j][2] = ((vv - fv) - m2)*is2;
            extra_s[grp][j][3] = ((fx - xx) - m3)*is3;
            extra_s[grp][j][4] = (edv - m4)*is4;
            extra_s[grp][j][5] = (edx - m5)*is5;
            extra_s[grp][j][6] = mc0[0];
            extra_s[grp][j][7] = mc0[1];
            extra_s[grp][j][8] = mc0[2];
        }
    }
    __syncthreads();

    auto build_h1 = [&](int grp){
        #pragma unroll 2
        for (int g=0; g<G_; g++){
            float a = base_s[grp][g][j];
            a = fmaf(extra_s[grp][g][0], w1e0, a);
            a = fmaf(extra_s[grp][g][1], w1e1, a);
            a = fmaf(extra_s[grp][g][2], w1e2, a);
            a = fmaf(extra_s[grp][g][3], w1e3, a);
            a = fmaf(extra_s[grp][g][4], w1e4, a);
            a = fmaf(extra_s[grp][g][5], w1e5, a);
            a = fmaf(extra_s[grp][g][6], w1m0, a);
            a = fmaf(extra_s[grp][g][7], w1m1, a);
            a = fmaf(extra_s[grp][g][8], w1m2, a);
            h1s[grp][g][j] = fmaxf(a, 0.3f*a);
        }
    };

    // t=0: half1 builds h1 group A (grp0), half2 builds group B (grp1)
    build_h1(half);
    __syncthreads();

    auto mlp2 = [&](int grp){
        #pragma unroll 2
        for (int g=0; g<G_; g++){
            float acc = matvec128(w, h1s[grp][g]) + bias;
            h2s[grp][g][j] = fmaxf(acc, 0.3f*acc);
        }
    };

    // prologue: h2 for group B, t=0
    if (half == 0) mlp2(1);
    __syncthreads();

    auto idm_act = [](float v, float dv, float dx,
                      float inv_desv, float tgap, float jamx, float mact, float invden)->float{
        float dxc = 0.1f + fmaxf(dx, 0.0f);
        float gap = fmaxf(fmaf(tgap, v, jamx) + v*dv*invden, 0.0f);
        float vr  = v*inv_desv; float vr2 = vr*vr;
        float gr  = gap/dxc;
        float a   = mact*(1.0f - vr2*vr2 - gr*gr);
        return fminf(fmaxf(a,-50.0f),50.0f);
    };

    auto phase2 = [&](int grp, int t){
        // prefetch this group's per-row step data (thread j<G_), hides under matvecs
        float s1,s2,s4,s5,s10, n1,n2,n4,n5,n10, c0,c1,c2;
        if (j < G_){
            int row = rowi_[grp];
            const float* sp = idm_s + ((size_t)row*T_ + t)*11;
            s1=sp[1]; s2=sp[2]; s4=sp[4]; s5=sp[5]; s10=sp[10];
            int tn = (t+1 < T_) ? (t+1) : (T_-1);
            const float* snp = idm_s + ((size_t)row*T_ + tn)*11;
            n1=snp[1]; n2=snp[2]; n4=snp[4]; n5=snp[5]; n10=snp[10];
            const float* mcp = mcs + ((size_t)row*T_ + tn)*3;
            c0=mcp[0]; c1=mcp[1]; c2=mcp[2];
        }
        const int wl = j >> 5;
        #pragma unroll 2
        for (int g=0; g<G_; g++){
            float acc = matvec128(w, h2s[grp][g]) + bias;
            float h3  = fmaxf(acc, 0.3f*acc);
            float pf = h3*wfj, pm = h3*wmj;
            #pragma unroll
            for (int o=16;o;o>>=1){
                pf += __shfl_xor_sync(0xffffffffu, pf, o);
                pm += __shfl_xor_sync(0xffffffffu, pm, o);
            }
            if ((j & 31)==0){ red_s[g][wl] = pf; red_s[g][4+wl] = pm; }
        }
        asm volatile("bar.sync 1, 128;" ::: "memory");   // half2-only
        if (j < G_){
            float lf = (red_s[j][0]+red_s[j][1]) + (red_s[j][2]+red_s[j][3]);
            float lm = (red_s[j][4]+red_s[j][5]) + (red_s[j][6]+red_s[j][7]);
            float d  = 5.0f*((lf + bfv) - (lm + bmv));
            float e  = expf(-d);
            float fatt = 1.0f/(1.0f+e);
            float matt = e*fatt;

            float vv = v_[grp], xx = x_[grp];
            bool  me = (s10 > 0.5f);
            float ef_dx = s4 - xx, ef_dv = vv - s1;
            float em_dx = me ? (s5 - xx) : 70.0f;
            float em_dv = me ? (vv - s2) : 0.0f;
            float efa = idm_act(vv, ef_dv, ef_dx, invdv_[grp], tgap_[grp], jamx_[grp], mact_[grp], invdn_[grp]);
            float ema = idm_act(vv, em_dv, em_dx, invdv_[grp], tgap_[grp], jamx_[grp], mact_[grp], invdn_[grp]);
            float act = fatt*efa + matt*ema;

            if (valid_[grp]){
                int o = rowi_[grp]*T_ + t;
                out[o]         = fminf(fmaxf(act,-5.4f),5.4f);
                out[BT_ + o]   = fatt;
                out[2*BT_ + o] = matt;
            }
            vv = fmaf(act, 0.1f, vv);
            xx = xx + vv*0.1f + act*0.005f;
            v_[grp] = vv; x_[grp] = xx;

            bool  men = (n10 > 0.5f);
            float edx = men ? (n5 - xx) : 70.0f;
            float edv = men ? (vv - n2) : 0.0f;
            extra_s[grp][j][0] = (vv - m0)*is0;
            extra_s[grp][j][1] = (n1 - m1)*is1;
            extra_s[grp][j][2] = ((vv - n1) - m2)*is2;
            extra_s[grp][j][3] = ((n4 - xx) - m3)*is3;
            extra_s[grp][j][4] = (edv - m4)*is4;
            extra_s[grp][j][5] = (edx - m5)*is5;
            extra_s[grp][j][6] = c0;
            extra_s[grp][j][7] = c1;
            extra_s[grp][j][8] = c2;
        }
        asm volatile("bar.sync 1, 128;" ::: "memory");
        build_h1(grp);   // h1 for next step (all 128 half2 threads)
    };

    for (int t = 0; t < T_; t++){
        // even phase: half1 -> h2 group A(t);  half2 -> h3 + epilogue group B(t)
        if (half == 0) mlp2(0); else phase2(1, t);
        __syncthreads();
        // odd phase:  half1 -> h2 group B(t+1); half2 -> h3 + epilogue group A(t)
        if (half == 0) mlp2(1); else phase2(0, t);
        __syncthreads();
    }
}

extern "C" void kernel_launch(void* const* d_in, const int* in_sizes, int n_in,
                              void* d_out, int out_size) {
    (void)in_sizes; (void)n_in; (void)out_size;
    const float* idm_params = (const float*)d_in[0];
    const float* pb         = (const float*)d_in[1];
    const float* eh         = (const float*)d_in[2];
    const float* idm_s      = (const float*)d_in[3];
    const float* mcs        = (const float*)d_in[4];
    const float* W1         = (const float*)d_in[5];
    const float* b1         = (const float*)d_in[6];
    const float* W2         = (const float*)d_in[7];
    const float* b2         = (const float*)d_in[8];
    const float* W3         = (const float*)d_in[9];
    const float* b3         = (const float*)d_in[10];
    const float* Wf         = (const float*)d_in[11];
    const float* bf         = (const float*)d_in[12];
    const float* Wm         = (const float*)d_in[13];
    const float* bm         = (const float*)d_in[14];
    const float* smean      = (const float*)d_in[15];
    const float* svar       = (const float*)d_in[16];
    float* out = (float*)d_out;

    base1_kernel<<<B_/16, 128>>>(pb, eh, W1, b1);
    rollout_kernel<<<NCTA, 256>>>(idm_params, idm_s, mcs, W1, W2, b2, W3, b3,
                                  Wf, bf, Wm, bm, smean, svar, out);
}